// round 1
// baseline (speedup 1.0000x reference)
#include <cuda_runtime.h>

#define NN 50000
#define EE 640000
#define GG 500
#define BN_EPS 1e-5f

// ---------------- scratch (static device globals; no allocation) ----------------
static __device__ __align__(16) float g_deg[NN];
static __device__ __align__(16) float g_dinv[NN];
static __device__ __align__(16) float g_dinv2[NN];
static __device__ __align__(16) int   g_cnt[NN];
static __device__ __align__(16) int   g_rowptr[NN];
static __device__ __align__(16) int   g_fill[NN];
static __device__ __align__(16) int   g_csrc[EE];
static __device__ __align__(16) float g_cnorm[EE];
static __device__ __align__(16) float g_s[NN];
static __device__ __align__(16) float g_h1[NN * 64];
static __device__ __align__(16) float g_t[NN * 128];
static __device__ __align__(16) float g_h2[NN * 128];
static __device__ __align__(16) float g_gsum[GG];
static __device__ __align__(16) int   g_gcnt[GG];

// ---------------- kernels ----------------

__global__ void k_zero() {
    int i = blockIdx.x * blockDim.x + threadIdx.x;
    if (i < NN) { g_deg[i] = 0.f; g_cnt[i] = 0; g_fill[i] = 0; }
    if (i < GG) { g_gsum[i] = 0.f; g_gcnt[i] = 0; }
}

// deg[dst] += w  and edge count histogram for CSR
__global__ void k_deg(const int* __restrict__ ei, const float* __restrict__ ea) {
    int e = blockIdx.x * blockDim.x + threadIdx.x;
    if (e >= EE) return;
    int d = ei[EE + e];
    atomicAdd(&g_deg[d], ea[e]);
    atomicAdd(&g_cnt[d], 1);
}

__global__ void k_dinv() {
    int n = blockIdx.x * blockDim.x + threadIdx.x;
    if (n >= NN) return;
    float r = rsqrtf(g_deg[n] + 1.0f);   // +1 self-loop weight
    g_dinv[n]  = r;
    g_dinv2[n] = r * r;
}

// single-block exclusive prefix sum over g_cnt -> g_rowptr
__global__ void k_scan() {
    __shared__ int sums[1024];
    const int tid = threadIdx.x;
    const int chunk = (NN + 1023) / 1024;   // 49
    int beg = tid * chunk;
    int end = min(beg + chunk, NN);
    int s = 0;
    for (int i = beg; i < end; i++) s += g_cnt[i];
    sums[tid] = s;
    __syncthreads();
    for (int off = 1; off < 1024; off <<= 1) {
        int v = (tid >= off) ? sums[tid - off] : 0;
        __syncthreads();
        sums[tid] += v;
        __syncthreads();
    }
    int run = (tid == 0) ? 0 : sums[tid - 1];
    for (int i = beg; i < end; i++) { g_rowptr[i] = run; run += g_cnt[i]; }
}

// build CSR: src index + precomputed norm = dinv[src]*w*dinv[dst]
__global__ void k_scatter(const int* __restrict__ ei, const float* __restrict__ ea) {
    int e = blockIdx.x * blockDim.x + threadIdx.x;
    if (e >= EE) return;
    int s = ei[e];
    int d = ei[EE + e];
    float w = ea[e];
    int pos = g_rowptr[d] + atomicAdd(&g_fill[d], 1);
    g_csrc[pos]  = s;
    g_cnorm[pos] = g_dinv[s] * w * g_dinv[d];
}

// layer-1: scalar aggregation (input dim = 1), plus per-graph node counts
__global__ void k_l1_agg(const float* __restrict__ x, const int* __restrict__ batch) {
    int n = blockIdx.x * blockDim.x + threadIdx.x;
    if (n >= NN) return;
    int beg = g_rowptr[n], end = beg + g_cnt[n];
    float acc = 0.f;
    for (int e = beg; e < end; e++)
        acc += g_cnorm[e] * __ldg(&x[g_csrc[e]]);
    acc += g_dinv2[n] * x[n];
    g_s[n] = acc;
    atomicAdd(&g_gcnt[batch[n]], 1);
}

// layer-1: outer product with W1 row + bias + BN + relu -> h1 [N,64]
__global__ void k_l1_bn(const float* __restrict__ W1, const float* __restrict__ b1,
                        const float* __restrict__ g1, const float* __restrict__ be1,
                        const float* __restrict__ m1, const float* __restrict__ v1) {
    int idx = blockIdx.x * blockDim.x + threadIdx.x;
    if (idx >= NN * 64) return;
    int f = idx & 63;
    int n = idx >> 6;
    float sc = g1[f] * rsqrtf(v1[f] + BN_EPS);
    float sh = be1[f] - m1[f] * sc;
    float val = fmaf(g_s[n], W1[f], b1[f]);
    val = fmaf(val, sc, sh);
    g_h1[idx] = fmaxf(val, 0.f);
}

// SIMT GEMM: Out[N,128] = A[N,K] @ W[K,128].  K=64 -> A=g_h1, K=128 -> A=g_h2.
// 128 threads/block, 32 nodes/block, each thread: 8 nodes x 4 features.
template<int K>
__global__ __launch_bounds__(128) void k_gemm(const float* __restrict__ W) {
    const float* __restrict__ A = (K == 64) ? g_h1 : g_h2;
    float* __restrict__ Out = g_t;

    __shared__ float Wsh[32 * 128];   // 16 KB chunk of W (32 k-rows)
    __shared__ float Hsh[32 * K];     // node tile

    const int tid = threadIdx.x;
    const int nb = blockIdx.x * 32;

    for (int i = tid; i < 32 * K; i += 128) {
        int m = i / K, k = i % K;
        int n = nb + m;
        Hsh[i] = (n < NN) ? A[n * K + k] : 0.f;
    }

    const int fq = tid & 31;   // feature quad -> f = fq*4
    const int mo = tid >> 5;   // node octet  -> m = mo*8 .. +7
    float acc[8][4];
#pragma unroll
    for (int j = 0; j < 8; j++) { acc[j][0] = acc[j][1] = acc[j][2] = acc[j][3] = 0.f; }

    const float* hb = &Hsh[(mo * 8) * K];

    for (int kk = 0; kk < K; kk += 32) {
        __syncthreads();
        for (int i = tid; i < 32 * 128; i += 128) Wsh[i] = W[kk * 128 + i];
        __syncthreads();
#pragma unroll 8
        for (int k2 = 0; k2 < 32; k2++) {
            float4 w = *(const float4*)&Wsh[k2 * 128 + fq * 4];
            int k = kk + k2;
#pragma unroll
            for (int j = 0; j < 8; j++) {
                float h = hb[j * K + k];
                acc[j][0] = fmaf(h, w.x, acc[j][0]);
                acc[j][1] = fmaf(h, w.y, acc[j][1]);
                acc[j][2] = fmaf(h, w.z, acc[j][2]);
                acc[j][3] = fmaf(h, w.w, acc[j][3]);
            }
        }
    }

#pragma unroll
    for (int j = 0; j < 8; j++) {
        int n = nb + mo * 8 + j;
        if (n < NN) {
            float4 st = make_float4(acc[j][0], acc[j][1], acc[j][2], acc[j][3]);
            *(float4*)&Out[n * 128 + fq * 4] = st;
        }
    }
}

// CSR gather for F=128: one warp per node, lane handles 4 features (float4).
// FINAL=false: layer 2 -> writes h2 (residual input).
// FINAL=true : layer 3 -> +residual, dot with Wf, warp-reduce, atomic into graph sums.
template<bool FINAL>
__global__ __launch_bounds__(256) void k_gather(
    const float* __restrict__ b, const float* __restrict__ g,
    const float* __restrict__ be, const float* __restrict__ m,
    const float* __restrict__ v, const float* __restrict__ Wf,
    const int* __restrict__ batch) {

    const float* __restrict__ t = g_t;
    int wid = (blockIdx.x * blockDim.x + threadIdx.x) >> 5;
    int lane = threadIdx.x & 31;
    if (wid >= NN) return;
    int n = wid;

    int beg = g_rowptr[n], end = beg + g_cnt[n];
    float ax = 0.f, ay = 0.f, az = 0.f, aw = 0.f;
    for (int e = beg; e < end; e++) {
        int s = g_csrc[e];
        float nm = g_cnorm[e];
        float4 tv = *(const float4*)&t[s * 128 + lane * 4];
        ax = fmaf(nm, tv.x, ax);
        ay = fmaf(nm, tv.y, ay);
        az = fmaf(nm, tv.z, az);
        aw = fmaf(nm, tv.w, aw);
    }
    float di = g_dinv2[n];
    float4 tn = *(const float4*)&t[n * 128 + lane * 4];
    ax = fmaf(di, tn.x, ax);
    ay = fmaf(di, tn.y, ay);
    az = fmaf(di, tn.z, az);
    aw = fmaf(di, tn.w, aw);

    float4 b4  = *(const float4*)&b[lane * 4];
    float4 g4  = *(const float4*)&g[lane * 4];
    float4 be4 = *(const float4*)&be[lane * 4];
    float4 m4  = *(const float4*)&m[lane * 4];
    float4 v4  = *(const float4*)&v[lane * 4];

    float scx = g4.x * rsqrtf(v4.x + BN_EPS);
    float scy = g4.y * rsqrtf(v4.y + BN_EPS);
    float scz = g4.z * rsqrtf(v4.z + BN_EPS);
    float scw = g4.w * rsqrtf(v4.w + BN_EPS);
    float rx = fmaxf(fmaf(ax + b4.x - m4.x, scx, be4.x), 0.f);
    float ry = fmaxf(fmaf(ay + b4.y - m4.y, scy, be4.y), 0.f);
    float rz = fmaxf(fmaf(az + b4.z - m4.z, scz, be4.z), 0.f);
    float rw = fmaxf(fmaf(aw + b4.w - m4.w, scw, be4.w), 0.f);

    if (FINAL) {
        float4 r4 = *(const float4*)&g_h2[n * 128 + lane * 4];
        rx += r4.x; ry += r4.y; rz += r4.z; rw += r4.w;
        float4 wf = *(const float4*)&Wf[lane * 4];
        float y = rx * wf.x + ry * wf.y + rz * wf.z + rw * wf.w;
#pragma unroll
        for (int off = 16; off; off >>= 1) y += __shfl_xor_sync(0xffffffffu, y, off);
        if (lane == 0) atomicAdd(&g_gsum[batch[n]], y);
    } else {
        *(float4*)&g_h2[n * 128 + lane * 4] = make_float4(rx, ry, rz, rw);
    }
}

__global__ void k_out(const float* __restrict__ bf, float* __restrict__ out) {
    int gidx = blockIdx.x * blockDim.x + threadIdx.x;
    if (gidx >= GG) return;
    out[gidx] = g_gsum[gidx] / fmaxf((float)g_gcnt[gidx], 1.f) + bf[0];
}

// ---------------- launch ----------------
extern "C" void kernel_launch(void* const* d_in, const int* in_sizes, int n_in,
                              void* d_out, int out_size) {
    const float* x   = (const float*)d_in[0];
    const int*   ei  = (const int*)d_in[1];
    const float* ea  = (const float*)d_in[2];
    const int*   bat = (const int*)d_in[3];
    const float* W1  = (const float*)d_in[4];
    const float* b1  = (const float*)d_in[5];
    const float* W2  = (const float*)d_in[6];
    const float* b2  = (const float*)d_in[7];
    const float* W3  = (const float*)d_in[8];
    const float* b3  = (const float*)d_in[9];
    const float* Wf  = (const float*)d_in[10];
    const float* bf  = (const float*)d_in[11];
    const float* g1  = (const float*)d_in[12];
    const float* be1 = (const float*)d_in[13];
    const float* m1  = (const float*)d_in[14];
    const float* v1  = (const float*)d_in[15];
    const float* g2  = (const float*)d_in[16];
    const float* be2 = (const float*)d_in[17];
    const float* m2  = (const float*)d_in[18];
    const float* v2  = (const float*)d_in[19];
    const float* g3  = (const float*)d_in[20];
    const float* be3 = (const float*)d_in[21];
    const float* m3  = (const float*)d_in[22];
    const float* v3  = (const float*)d_in[23];
    float* out = (float*)d_out;

    k_zero<<<(NN + 255) / 256, 256>>>();
    k_deg<<<(EE + 255) / 256, 256>>>(ei, ea);
    k_dinv<<<(NN + 255) / 256, 256>>>();
    k_scan<<<1, 1024>>>();
    k_scatter<<<(EE + 255) / 256, 256>>>(ei, ea);

    // layer 1 (scalar agg + BN/relu)
    k_l1_agg<<<(NN + 255) / 256, 256>>>(x, bat);
    k_l1_bn<<<(NN * 64 + 255) / 256, 256>>>(W1, b1, g1, be1, m1, v1);

    // layer 2: t = h1 @ W2 ; gather -> h2 (residual)
    k_gemm<64><<<(NN + 31) / 32, 128>>>(W2);
    k_gather<false><<<(NN * 32 + 255) / 256, 256>>>(b2, g2, be2, m2, v2, Wf, bat);

    // layer 3: t = h2 @ W3 ; gather + residual + Wf dot + graph pool (fused)
    k_gemm<128><<<(NN + 31) / 32, 128>>>(W3);
    k_gather<true><<<(NN * 32 + 255) / 256, 256>>>(b3, g3, be3, m3, v3, Wf, bat);

    k_out<<<(GG + 255) / 256, 256>>>(bf, out);
}